// round 16
// baseline (speedup 1.0000x reference)
#include <cuda_runtime.h>
#include <cuda_bf16.h>
#include <math_constants.h>
#include <cstdint>

// ---------------------------------------------------------------------------
// RVQBottleneck: 2-stage residual VQ via mma.sync bf16 m16n8k16 3-term split.
//   reference dist = fl( fl(x2 + e2) - 2*xe ), argmin first-index tie break.
//   stage tracks dd' = fl(e2) - 2*xe_bf16 (x2-invariant ordering);
//   top-2 (value+index); near-ties (gap <= MARGIN) rescored in-kernel for the
//   {i1,i2} pair with the exact reference expression tree (fp32, first-index
//   ties). Stage 2 recomputes the residual row on the fly (no fp32 buffer).
// WARP-AUTONOMOUS MAINLOOP: each warp double-buffers its own A(32row)+B(64row)
// fragments in a private smem region via its own cp.async groups; the only
// mainloop synchronization is the warp's own wait_group + __syncwarp.
// No __syncthreads until the final cross-warp reduction.
// Packed layout per row / 16-k block (16 words): word[4t+0]=hi(2t,2t+1),
// [4t+1]=mid(2t,2t+1), [4t+2]=hi(2t+8,2t+9), [4t+3]=mid(2t+8,2t+9).
// Smem rows are 16 words; uint4 slot c stored at c ^ (row & 3) -> conflict-
// free for both the store pattern and frag loads (frag rows share key gid&3).
// ---------------------------------------------------------------------------

#define D        512
#define MAXROWS  32768
#define NCMAX    1024

#define BM   128
#define WPR  512
#define MARGIN 2.5e-4f

// per-warp region: 2 buffers x (A 512 + B 1024 words) = 3072 words = 12KB
#define WARP_WORDS 3072u
#define SMEM_DYN   (8 * WARP_WORDS * 4)   // 98304 bytes

// ---- scratch (allocation-free) --------------------------------------------
__device__ uint32_t g_apk[(size_t)MAXROWS * WPR];
__device__ uint32_t g_e0pk[(size_t)NCMAX * WPR];
__device__ uint32_t g_e1pk[(size_t)NCMAX * WPR];
__device__ float    g_x2[MAXROWS];
__device__ float    g_r2[MAXROWS];
__device__ float    g_e2a[NCMAX];
__device__ float    g_e2b[NCMAX];
__device__ int      g_idx0[MAXROWS];
__device__ int      g_idx1[MAXROWS];

// ---- helpers --------------------------------------------------------------
__device__ __forceinline__ uint32_t bf16pack(float lo, float hi_) {
    uint32_t r;
    asm("cvt.rn.bf16x2.f32 %0, %1, %2;" : "=r"(r) : "f"(hi_), "f"(lo));
    return r;
}
__device__ __forceinline__ float bf16round(float x) {
    return __bfloat162float(__float2bfloat16(x));
}
#define CPASYNC16(dst, src) \
    asm volatile("cp.async.cg.shared.global [%0], [%1], 16;" :: "r"(dst), "l"(src) : "memory")
#define CPCOMMIT() asm volatile("cp.async.commit_group;" ::: "memory")
#define CPWAIT(n)  asm volatile("cp.async.wait_group %0;" :: "n"(n) : "memory")

#define MMA_BF16(d, a, b0, b1) \
    asm volatile("mma.sync.aligned.m16n8k16.row.col.f32.bf16.bf16.f32 " \
        "{%0,%1,%2,%3}, {%4,%5,%6,%7}, {%8,%9}, {%0,%1,%2,%3};" \
        : "+f"((d)[0]), "+f"((d)[1]), "+f"((d)[2]), "+f"((d)[3]) \
        : "r"((a)[0]), "r"((a)[1]), "r"((a)[2]), "r"((a)[3]), "r"(b0), "r"(b1))

__device__ __forceinline__ uint32_t smem_u32_of(const void* p) {
    uint32_t a;
    asm("{ .reg .u64 t; cvta.to.shared.u64 t, %1; cvt.u32.u64 %0, t; }"
        : "=r"(a) : "l"(p));
    return a;
}

// merge two (top1, top2) records; value-order only (ties resolved by rescue)
__device__ __forceinline__ void merge2(float& d1, int& i1, float& d2, int& i2,
                                       float pd1, int pi1, float pd2, int pi2)
{
    if (pd1 < d1) {
        if (d1 <= pd2) { d2 = d1;  i2 = i1;  }
        else           { d2 = pd2; i2 = pi2; }
        d1 = pd1; i1 = pi1;
    } else if (pd1 < d2) {
        d2 = pd1; i2 = pi1;
    }
}

// ---------------------------------------------------------------------------
// Pack fp32 -> interleaved bf16 hi/mid words (16 elems per lane).
// ---------------------------------------------------------------------------
__device__ __forceinline__ void pack16(const float* __restrict__ s, uint4* d)
{
    float f[16];
    float4 F0 = ((const float4*)s)[0], F1 = ((const float4*)s)[1];
    float4 F2 = ((const float4*)s)[2], F3 = ((const float4*)s)[3];
    f[0]=F0.x; f[1]=F0.y; f[2]=F0.z; f[3]=F0.w;
    f[4]=F1.x; f[5]=F1.y; f[6]=F1.z; f[7]=F1.w;
    f[8]=F2.x; f[9]=F2.y; f[10]=F2.z; f[11]=F2.w;
    f[12]=F3.x; f[13]=F3.y; f[14]=F3.z; f[15]=F3.w;
#pragma unroll
    for (int t = 0; t < 4; ++t) {
        float x0 = f[2*t],   x1 = f[2*t+1];
        float x2 = f[2*t+8], x3 = f[2*t+9];
        uint4 w;
        w.x = bf16pack(x0, x1);
        w.y = bf16pack(x0 - bf16round(x0), x1 - bf16round(x1));
        w.z = bf16pack(x2, x3);
        w.w = bf16pack(x2 - bf16round(x2), x3 - bf16round(x3));
        d[t] = w;
    }
}

// ---------------------------------------------------------------------------
// Fused pack + row-norm for x, e0, e1 in one launch. One warp per row.
// ---------------------------------------------------------------------------
__global__ void packnorm3_kernel(const float* __restrict__ x,  uint32_t* __restrict__ xpk,  float* __restrict__ xn,
                                 const float* __restrict__ e0, uint32_t* __restrict__ e0pk, float* __restrict__ e0n,
                                 const float* __restrict__ e1, uint32_t* __restrict__ e1pk, float* __restrict__ e1n,
                                 int rows, int nc)
{
    int gr = blockIdx.x * 8 + (threadIdx.x >> 5);
    const float* src; uint32_t* dpk; float* dn; int row;
    if (gr < rows)             { src = x;  dpk = xpk;  dn = xn;  row = gr; }
    else if (gr < rows + nc)   { src = e0; dpk = e0pk; dn = e0n; row = gr - rows; }
    else if (gr < rows + 2*nc) { src = e1; dpk = e1pk; dn = e1n; row = gr - rows - nc; }
    else return;
    int lane = threadIdx.x & 31;
    const float4* p = (const float4*)(src + (size_t)row * D);
    float s = 0.f;
#pragma unroll
    for (int i = 0; i < D / 128; i++) {
        float4 v = p[lane + 32 * i];
        s += v.x * v.x + v.y * v.y + v.z * v.z + v.w * v.w;
    }
#pragma unroll
    for (int o = 16; o; o >>= 1) s += __shfl_down_sync(0xFFFFFFFFu, s, o);
    if (lane == 0) dn[row] = s;

    pack16(src + (size_t)row * D + lane * 16,
           (uint4*)(dpk + (size_t)row * WPR + lane * 16));
}

// ---------------------------------------------------------------------------
// Fused bf16-MMA GEMM + argmin stage. 256 thr, warp tile 32x64, BM=128.
// 16-k chunks, per-warp double-buffered private smem, no block barriers.
// ---------------------------------------------------------------------------
__global__ __launch_bounds__(256, 2)
void stage_mma_kernel(const uint32_t* __restrict__ Apk,
                      const uint32_t* __restrict__ Bpk,
                      const float* __restrict__ X,
                      const float* __restrict__ Eprev, const int* __restrict__ idxPrev,
                      const float* __restrict__ Ecur,
                      const float* __restrict__ rn2, const float* __restrict__ en2,
                      int* __restrict__ outIdx, int ncodes)
{
    extern __shared__ uint32_t SM[];

    const int tid  = threadIdx.x;
    const int lane = tid & 31;
    const int wid  = tid >> 5;
    const int wm   = wid & 3;
    const int wn   = wid >> 2;
    const int gid  = lane >> 2;
    const int tig  = lane & 3;
    const int rowBase = blockIdx.x * BM;

    uint32_t*      W  = SM + (uint32_t)wid * WARP_WORDS;   // private region
    const uint32_t wA = smem_u32_of(W);

    const uint32_t* Abase = Apk + (size_t)(rowBase + wm * 32) * WPR;
    const uint32_t* Bbase = Bpk + (size_t)(wn * 64) * WPR;

    // precomputed lane slots for cp.async (row = s>>2, c = s&3, sc = c^(row&3))
    const int keyg = gid & 3;

    float b1d[4], b2d[4];
    int   b1i[4], b2i[4];
#pragma unroll
    for (int s = 0; s < 4; ++s) {
        b1d[s] = CUDART_INF_F; b1i[s] = 0;
        b2d[s] = CUDART_INF_F; b2i[s] = 0x7FFFFFFF;
    }

    float acc[2][8][4];

    const int NCT = ncodes >> 7;
    const int NIT = NCT * 32;          // 16-k chunks

#define ISSUE_CHUNK(g) do {                                                    \
    const uint32_t kb_ = (uint32_t)((g) & 31) * 16u;                           \
    const uint32_t cb_ = (uint32_t)((g) >> 5) * 128u;                          \
    const uint32_t buf_ = wA + (uint32_t)((g) & 1) * 6144u;                    \
    _Pragma("unroll")                                                          \
    for (int i_ = 0; i_ < 4; ++i_) {                                           \
        int s_ = lane + 32 * i_;                                               \
        int r_ = s_ >> 2, c_ = s_ & 3;                                         \
        uint32_t sc_ = (uint32_t)(c_ ^ (r_ & 3));                              \
        CPASYNC16(buf_ + (uint32_t)(r_ * 16 + sc_ * 4) * 4,                    \
                  Abase + (size_t)r_ * WPR + kb_ + c_ * 4);                    \
    }                                                                          \
    _Pragma("unroll")                                                          \
    for (int i_ = 0; i_ < 8; ++i_) {                                           \
        int s_ = lane + 32 * i_;                                               \
        int r_ = s_ >> 2, c_ = s_ & 3;                                         \
        uint32_t sc_ = (uint32_t)(c_ ^ (r_ & 3));                              \
        CPASYNC16(buf_ + 2048u + (uint32_t)(r_ * 16 + sc_ * 4) * 4,            \
                  Bbase + (size_t)(cb_ + r_) * WPR + kb_ + c_ * 4);            \
    }                                                                          \
    CPCOMMIT();                                                                \
} while (0)

    ISSUE_CHUNK(0);

    for (int it = 0; it < NIT; ++it) {
        if (it + 1 < NIT) { ISSUE_CHUNK(it + 1); CPWAIT(1); }
        else              { CPWAIT(0); }
        __syncwarp();

        if ((it & 31) == 0) {
#pragma unroll
            for (int mt = 0; mt < 2; ++mt)
#pragma unroll
                for (int nt = 0; nt < 8; ++nt)
#pragma unroll
                    for (int c = 0; c < 4; ++c) acc[mt][nt][c] = 0.f;
        }

        {
            const uint32_t* A = W + (uint32_t)(it & 1) * 1536u;
            const uint32_t* B = A + 512;
            const int j0 = (tig ^ keyg) * 4;
            uint32_t ah[2][4], am[2][4];
#pragma unroll
            for (int mt = 0; mt < 2; ++mt) {
                const int r = mt * 16 + gid;
                uint4 v = *(const uint4*)(A + r * 16 + j0);
                uint4 w = *(const uint4*)(A + (r + 8) * 16 + j0);
                ah[mt][0] = v.x; am[mt][0] = v.y; ah[mt][2] = v.z; am[mt][2] = v.w;
                ah[mt][1] = w.x; am[mt][1] = w.y; ah[mt][3] = w.z; am[mt][3] = w.w;
            }
#pragma unroll
            for (int nt = 0; nt < 8; ++nt) {
                const int cr = nt * 8 + gid;
                uint4 b = *(const uint4*)(B + cr * 16 + j0);
#pragma unroll
                for (int mt = 0; mt < 2; ++mt) {
                    MMA_BF16(acc[mt][nt], ah[mt], b.x, b.z);   // h*h
                    MMA_BF16(acc[mt][nt], ah[mt], b.y, b.w);   // h*m
                    MMA_BF16(acc[mt][nt], am[mt], b.x, b.z);   // m*h
                }
            }
        }

        if ((it & 31) == 31) {
            const int ct = it >> 5;
#pragma unroll
            for (int mt = 0; mt < 2; ++mt)
#pragma unroll
                for (int nt = 0; nt < 8; ++nt)
#pragma unroll
                    for (int c = 0; c < 4; ++c) {
                        const int col = ct * 128 + wn * 64 + nt * 8 + tig * 2 + (c & 1);
                        const int s   = mt * 2 + (c >> 1);
                        // x2-invariant ordering metric: e2 - 2*xe
                        float dd = __fmaf_rn(-2.0f, acc[mt][nt][c], __ldg(&en2[col]));
                        bool p = dd < b1d[s];
                        bool q = dd < b2d[s];
                        b2d[s] = p ? b1d[s] : (q ? dd  : b2d[s]);
                        b2i[s] = p ? b1i[s] : (q ? col : b2i[s]);
                        b1d[s] = p ? dd  : b1d[s];
                        b1i[s] = p ? col : b1i[s];
                    }
        }
    }
#undef ISSUE_CHUNK

    // mainloop done for all warps; alias reduction arrays onto SM
    __syncthreads();
    float* sd1 = (float*)&SM[0];
    int*   si1 = (int*)  &SM[256];
    float* sd2 = (float*)&SM[512];
    int*   si2 = (int*)  &SM[768];

    // ---- reduction: across tig (shfl), then across warp_n (smem) ----
#pragma unroll
    for (int s = 0; s < 4; ++s) {
        float d1 = b1d[s], d2 = b2d[s];
        int   i1 = b1i[s], i2 = b2i[s];
#pragma unroll
        for (int off = 1; off < 4; off <<= 1) {
            float pd1 = __shfl_xor_sync(0xFFFFFFFFu, d1, off);
            int   pi1 = __shfl_xor_sync(0xFFFFFFFFu, i1, off);
            float pd2 = __shfl_xor_sync(0xFFFFFFFFu, d2, off);
            int   pi2 = __shfl_xor_sync(0xFFFFFFFFu, i2, off);
            merge2(d1, i1, d2, i2, pd1, pi1, pd2, pi2);
        }
        if (tig == 0) {
            const int row = wm * 32 + (s >> 1) * 16 + (s & 1) * 8 + gid;
            sd1[wn * 128 + row] = d1;  si1[wn * 128 + row] = i1;
            sd2[wn * 128 + row] = d2;  si2[wn * 128 + row] = i2;
        }
    }
    __syncthreads();

    if (tid < 128) {
        float d1 = sd1[tid], d2 = sd2[tid];
        int   i1 = si1[tid], i2 = si2[tid];
        merge2(d1, i1, d2, i2,
               sd1[128 + tid], si1[128 + tid], sd2[128 + tid], si2[128 + tid]);

        int winner = i1;
        if (d2 - d1 <= MARGIN) {
            // exact reference rescore of the near-tied pair
            const int row = rowBase + tid;
            int ia = min(i1, i2), ib = max(i1, i2);
            const float4* xr = (const float4*)(X + (size_t)row * D);
            const float4* ea = (const float4*)(Ecur + (size_t)ia * D);
            const float4* eb = (const float4*)(Ecur + (size_t)ib * D);
            float x2v = __ldg(&rn2[row]);
            float xea = 0.f, xeb = 0.f;
            if (idxPrev) {
                const float4* pr = (const float4*)(Eprev + (size_t)__ldg(&idxPrev[row]) * D);
                for (int k = 0; k < D / 4; ++k) {
                    float4 xv = __ldg(&xr[k]);
                    float4 pv = __ldg(&pr[k]);
                    float4 rv = make_float4(xv.x - pv.x, xv.y - pv.y,
                                            xv.z - pv.z, xv.w - pv.w);
                    float4 av = __ldg(&ea[k]);
                    float4 bv = __ldg(&eb[k]);
                    xea = __fmaf_rn(rv.x, av.x, xea); xea = __fmaf_rn(rv.y, av.y, xea);
                    xea = __fmaf_rn(rv.z, av.z, xea); xea = __fmaf_rn(rv.w, av.w, xea);
                    xeb = __fmaf_rn(rv.x, bv.x, xeb); xeb = __fmaf_rn(rv.y, bv.y, xeb);
                    xeb = __fmaf_rn(rv.z, bv.z, xeb); xeb = __fmaf_rn(rv.w, bv.w, xeb);
                }
            } else {
                for (int k = 0; k < D / 4; ++k) {
                    float4 rv = __ldg(&xr[k]);
                    float4 av = __ldg(&ea[k]);
                    float4 bv = __ldg(&eb[k]);
                    xea = __fmaf_rn(rv.x, av.x, xea); xea = __fmaf_rn(rv.y, av.y, xea);
                    xea = __fmaf_rn(rv.z, av.z, xea); xea = __fmaf_rn(rv.w, av.w, xea);
                    xeb = __fmaf_rn(rv.x, bv.x, xeb); xeb = __fmaf_rn(rv.y, bv.y, xeb);
                    xeb = __fmaf_rn(rv.z, bv.z, xeb); xeb = __fmaf_rn(rv.w, bv.w, xeb);
                }
            }
            float da = __fmaf_rn(-2.f, xea, __fadd_rn(x2v, __ldg(&en2[ia])));
            float db = __fmaf_rn(-2.f, xeb, __fadd_rn(x2v, __ldg(&en2[ib])));
            winner = (db < da) ? ib : ia;   // tie -> lower index ia
        }
        outIdx[rowBase + tid] = winner;
    }
}

// ---------------------------------------------------------------------------
// Fused: residual = X - E[idx] (exact fp32) -> packed bf16 words + ||R||^2.
// ---------------------------------------------------------------------------
__global__ void residpack_kernel(const float* __restrict__ X, const float* __restrict__ E,
                                 const int* __restrict__ idx,
                                 uint32_t* __restrict__ Rpk, float* __restrict__ r2)
{
    int row = blockIdx.x;
    int t   = threadIdx.x;     // 0..127
    int c   = idx[row];
    float4 xv = ((const float4*)(X + (size_t)row * D))[t];
    float4 ev = ((const float4*)(E + (size_t)c   * D))[t];
    float4 rv = make_float4(xv.x - ev.x, xv.y - ev.y, xv.z - ev.z, xv.w - ev.w);

    {
        uint32_t* dst = Rpk + (size_t)row * WPR;
        int blk = t >> 2;
        int a   = t & 3;
        uint32_t whi0 = bf16pack(rv.x, rv.y);
        uint32_t wmi0 = bf16pack(rv.x - bf16round(rv.x), rv.y - bf16round(rv.y));
        uint32_t whi1 = bf16pack(rv.z, rv.w);
        uint32_t wmi1 = bf16pack(rv.z - bf16round(rv.z), rv.w - bf16round(rv.w));
        int w0 = (a < 2) ? 8 * a     : 8 * (a - 2) + 2;
        int w1 = (a < 2) ? 8 * a + 4 : 8 * (a - 2) + 6;
        dst[blk * 16 + w0]     = whi0;
        dst[blk * 16 + w0 + 1] = wmi0;
        dst[blk * 16 + w1]     = whi1;
        dst[blk * 16 + w1 + 1] = wmi1;
    }

    float s = rv.x * rv.x + rv.y * rv.y + rv.z * rv.z + rv.w * rv.w;
#pragma unroll
    for (int o = 16; o; o >>= 1) s += __shfl_down_sync(0xFFFFFFFFu, s, o);
    __shared__ float red[4];
    if ((t & 31) == 0) red[t >> 5] = s;
    __syncthreads();
    if (t == 0) r2[row] = red[0] + red[1] + red[2] + red[3];
}

// ---------------------------------------------------------------------------
// Output: out = fl(x + fl(fl(e0+e1) - x))  (reference STE rounding)
// ---------------------------------------------------------------------------
__global__ void out_kernel(const float* __restrict__ X, const float* __restrict__ E0,
                           const float* __restrict__ E1, const int* __restrict__ i0,
                           const int* __restrict__ i1, float* __restrict__ out)
{
    int row = blockIdx.x;
    int t   = threadIdx.x;
    int c0  = i0[row];
    int c1  = i1[row];
    float4 xv = ((const float4*)(X  + (size_t)row * D))[t];
    float4 a  = ((const float4*)(E0 + (size_t)c0  * D))[t];
    float4 b  = ((const float4*)(E1 + (size_t)c1  * D))[t];
    float4 o;
    o.x = __fadd_rn(xv.x, __fadd_rn(__fadd_rn(a.x, b.x), -xv.x));
    o.y = __fadd_rn(xv.y, __fadd_rn(__fadd_rn(a.y, b.y), -xv.y));
    o.z = __fadd_rn(xv.z, __fadd_rn(__fadd_rn(a.z, b.z), -xv.z));
    o.w = __fadd_rn(xv.w, __fadd_rn(__fadd_rn(a.w, b.w), -xv.w));
    ((float4*)(out + (size_t)row * D))[t] = o;
}

// ---------------------------------------------------------------------------
extern "C" void kernel_launch(void* const* d_in, const int* in_sizes, int n_in,
                              void* d_out, int out_size)
{
    const float* x  = (const float*)d_in[0];
    const float* e0 = (const float*)d_in[1];
    const float* e1 = (const float*)d_in[2];
    float* out = (float*)d_out;

    int rows = in_sizes[0] / D;   // 32768
    int nc   = in_sizes[1] / D;   // 1024

    uint32_t *papk, *pe0pk, *pe1pk;
    float *px2, *pr2, *pe2a, *pe2b;
    int   *pi0, *pi1;
    cudaGetSymbolAddress((void**)&papk,  g_apk);
    cudaGetSymbolAddress((void**)&pe0pk, g_e0pk);
    cudaGetSymbolAddress((void**)&pe1pk, g_e1pk);
    cudaGetSymbolAddress((void**)&px2,   g_x2);
    cudaGetSymbolAddress((void**)&pr2,   g_r2);
    cudaGetSymbolAddress((void**)&pe2a,  g_e2a);
    cudaGetSymbolAddress((void**)&pe2b,  g_e2b);
    cudaGetSymbolAddress((void**)&pi0,   g_idx0);
    cudaGetSymbolAddress((void**)&pi1,   g_idx1);

    cudaFuncSetAttribute(stage_mma_kernel,
                         cudaFuncAttributeMaxDynamicSharedMemorySize, SMEM_DYN);

    packnorm3_kernel<<<(rows + 2 * nc + 7) / 8, 256>>>(x, papk, px2,
                                                       e0, pe0pk, pe2a,
                                                       e1, pe1pk, pe2b,
                                                       rows, nc);
    stage_mma_kernel<<<rows / BM, 256, SMEM_DYN>>>(papk, pe0pk,
                                                   x, nullptr, nullptr, e0,
                                                   px2, pe2a, pi0, nc);
    residpack_kernel<<<rows, 128>>>(x, e0, pi0, papk, pr2);
    stage_mma_kernel<<<rows / BM, 256, SMEM_DYN>>>(papk, pe1pk,
                                                   x, e0, pi0, e1,
                                                   pr2, pe2b, pi1, nc);
    out_kernel<<<rows, 128>>>(x, e0, e1, pi0, pi1, out);
}

// round 17
// speedup vs baseline: 1.2105x; 1.2105x over previous
#include <cuda_runtime.h>
#include <cuda_bf16.h>
#include <math_constants.h>
#include <cstdint>

// ---------------------------------------------------------------------------
// RVQBottleneck: 2-stage residual VQ via mma.sync bf16 m16n8k16 3-term split.
//   reference dist = fl( fl(x2 + e2) - 2*xe ), argmin first-index tie break.
//   stage tracks dd' = fl(e2) - 2*xe_bf16 (x2-invariant ordering);
//   top-2 (value+index); near-ties (gap <= MARGIN) rescored in-kernel for the
//   {i1,i2} pair with the exact reference expression tree (fp32, first-index
//   ties). Stage 2 recomputes the residual row on the fly (no fp32 buffer)
//   and writes the final output in its tail (out_kernel folded in).
// Engine identical to round 13 (best measured: 411 us/stage, rel_err 0.0).
// Packed layout per row / 16-k block (16 words): word[4t+0]=hi(2t,2t+1),
// [4t+1]=mid(2t,2t+1), [4t+2]=hi(2t+8,2t+9), [4t+3]=mid(2t+8,2t+9).
// ---------------------------------------------------------------------------

#define D        512
#define MAXROWS  32768
#define NCMAX    1024

#define BM   128
#define WPR  512
#define MARGIN 2.5e-4f

#define BUF_WORDS 8192u            // per stream buffer: A 4096 + B 4096 words
#define SMEM_DYN  (3 * BUF_WORDS * 4)   // 98304 bytes

// ---- scratch (allocation-free) --------------------------------------------
__device__ uint32_t g_apk[(size_t)MAXROWS * WPR];
__device__ uint32_t g_e0pk[(size_t)NCMAX * WPR];
__device__ uint32_t g_e1pk[(size_t)NCMAX * WPR];
__device__ float    g_x2[MAXROWS];
__device__ float    g_r2[MAXROWS];
__device__ float    g_e2a[NCMAX];
__device__ float    g_e2b[NCMAX];
__device__ int      g_idx0[MAXROWS];
__device__ int      g_idx1[MAXROWS];

// ---- helpers --------------------------------------------------------------
__device__ __forceinline__ uint32_t bf16pack(float lo, float hi_) {
    uint32_t r;
    asm("cvt.rn.bf16x2.f32 %0, %1, %2;" : "=r"(r) : "f"(hi_), "f"(lo));
    return r;
}
__device__ __forceinline__ float bf16round(float x) {
    return __bfloat162float(__float2bfloat16(x));
}
#define CPASYNC16(dst, src) \
    asm volatile("cp.async.cg.shared.global [%0], [%1], 16;" :: "r"(dst), "l"(src) : "memory")
#define CPCOMMIT() asm volatile("cp.async.commit_group;" ::: "memory")
#define CPWAIT(n)  asm volatile("cp.async.wait_group %0;" :: "n"(n) : "memory")

#define MMA_BF16(d, a, b0, b1) \
    asm volatile("mma.sync.aligned.m16n8k16.row.col.f32.bf16.bf16.f32 " \
        "{%0,%1,%2,%3}, {%4,%5,%6,%7}, {%8,%9}, {%0,%1,%2,%3};" \
        : "+f"((d)[0]), "+f"((d)[1]), "+f"((d)[2]), "+f"((d)[3]) \
        : "r"((a)[0]), "r"((a)[1]), "r"((a)[2]), "r"((a)[3]), "r"(b0), "r"(b1))

__device__ __forceinline__ uint32_t smem_u32_of(const void* p) {
    uint32_t a;
    asm("{ .reg .u64 t; cvta.to.shared.u64 t, %1; cvt.u32.u64 %0, t; }"
        : "=r"(a) : "l"(p));
    return a;
}

// merge two (top1, top2) records; value-order only (ties resolved by rescue)
__device__ __forceinline__ void merge2(float& d1, int& i1, float& d2, int& i2,
                                       float pd1, int pi1, float pd2, int pi2)
{
    if (pd1 < d1) {
        if (d1 <= pd2) { d2 = d1;  i2 = i1;  }
        else           { d2 = pd2; i2 = pi2; }
        d1 = pd1; i1 = pi1;
    } else if (pd1 < d2) {
        d2 = pd1; i2 = pi1;
    }
}

// ---------------------------------------------------------------------------
// Pack fp32 -> interleaved bf16 hi/mid words (16 elems per lane).
// ---------------------------------------------------------------------------
__device__ __forceinline__ void pack16(const float* __restrict__ s, uint4* d)
{
    float f[16];
    float4 F0 = ((const float4*)s)[0], F1 = ((const float4*)s)[1];
    float4 F2 = ((const float4*)s)[2], F3 = ((const float4*)s)[3];
    f[0]=F0.x; f[1]=F0.y; f[2]=F0.z; f[3]=F0.w;
    f[4]=F1.x; f[5]=F1.y; f[6]=F1.z; f[7]=F1.w;
    f[8]=F2.x; f[9]=F2.y; f[10]=F2.z; f[11]=F2.w;
    f[12]=F3.x; f[13]=F3.y; f[14]=F3.z; f[15]=F3.w;
#pragma unroll
    for (int t = 0; t < 4; ++t) {
        float x0 = f[2*t],   x1 = f[2*t+1];
        float x2 = f[2*t+8], x3 = f[2*t+9];
        uint4 w;
        w.x = bf16pack(x0, x1);
        w.y = bf16pack(x0 - bf16round(x0), x1 - bf16round(x1));
        w.z = bf16pack(x2, x3);
        w.w = bf16pack(x2 - bf16round(x2), x3 - bf16round(x3));
        d[t] = w;
    }
}

// ---------------------------------------------------------------------------
// Fused pack + row-norm for x, e0, e1 in one launch. One warp per row.
// ---------------------------------------------------------------------------
__global__ void packnorm3_kernel(const float* __restrict__ x,  uint32_t* __restrict__ xpk,  float* __restrict__ xn,
                                 const float* __restrict__ e0, uint32_t* __restrict__ e0pk, float* __restrict__ e0n,
                                 const float* __restrict__ e1, uint32_t* __restrict__ e1pk, float* __restrict__ e1n,
                                 int rows, int nc)
{
    int gr = blockIdx.x * 8 + (threadIdx.x >> 5);
    const float* src; uint32_t* dpk; float* dn; int row;
    if (gr < rows)             { src = x;  dpk = xpk;  dn = xn;  row = gr; }
    else if (gr < rows + nc)   { src = e0; dpk = e0pk; dn = e0n; row = gr - rows; }
    else if (gr < rows + 2*nc) { src = e1; dpk = e1pk; dn = e1n; row = gr - rows - nc; }
    else return;
    int lane = threadIdx.x & 31;
    const float4* p = (const float4*)(src + (size_t)row * D);
    float s = 0.f;
#pragma unroll
    for (int i = 0; i < D / 128; i++) {
        float4 v = p[lane + 32 * i];
        s += v.x * v.x + v.y * v.y + v.z * v.z + v.w * v.w;
    }
#pragma unroll
    for (int o = 16; o; o >>= 1) s += __shfl_down_sync(0xFFFFFFFFu, s, o);
    if (lane == 0) dn[row] = s;

    pack16(src + (size_t)row * D + lane * 16,
           (uint4*)(dpk + (size_t)row * WPR + lane * 16));
}

// ---------------------------------------------------------------------------
// Fused bf16-MMA GEMM + argmin stage. 256 thr, warp tile 32x64, BM=128.
// 32-k chunks, triple buffered (dynamic smem), one barrier per chunk.
// Round-13 engine verbatim. If outBuf != nullptr (stage 2), the tail also
// writes the final STE output for the CTA's 128 rows (out_kernel folded in).
// ---------------------------------------------------------------------------
__global__ __launch_bounds__(256, 2)
void stage_mma_kernel(const uint32_t* __restrict__ Apk,
                      const uint32_t* __restrict__ Bpk,
                      const float* __restrict__ X,
                      const float* __restrict__ Eprev, const int* __restrict__ idxPrev,
                      const float* __restrict__ Ecur,
                      const float* __restrict__ rn2, const float* __restrict__ en2,
                      int* __restrict__ outIdx, int ncodes,
                      float* __restrict__ outBuf)
{
    extern __shared__ uint32_t SM[];
    const uint32_t sA = smem_u32_of(SM);

    const int tid  = threadIdx.x;
    const int lane = tid & 31;
    const int wid  = tid >> 5;
    const int wm   = wid & 3;
    const int wn   = wid >> 2;
    const int gid  = lane >> 2;
    const int tig  = lane & 3;
    const int rowBase = blockIdx.x * BM;

    // per-thread cp.async geometry: u = tid + 256*m -> row = row0+32m, c = tid&7
    const int row0 = tid >> 3;
    const int c0   = tid & 7;
    const int keyS = ((row0 & 1) << 2) | ((row0 >> 1) & 3);
    const uint32_t aD0 = (uint32_t)(row0 * 32 + ((c0 ^ keyS) << 2));   // word off
    const uint32_t* As0 = Apk + (size_t)(rowBase + row0) * WPR + c0 * 4;
    const uint32_t* Bs0 = Bpk + (size_t)row0 * WPR + c0 * 4;

    const int keyg = ((gid & 1) << 2) | ((gid >> 1) & 3);

    float b1d[4], b2d[4];
    int   b1i[4], b2i[4];
#pragma unroll
    for (int s = 0; s < 4; ++s) {
        b1d[s] = CUDART_INF_F; b1i[s] = 0;
        b2d[s] = CUDART_INF_F; b2i[s] = 0x7FFFFFFF;
    }

    float acc[2][8][4];

    const int NCT = ncodes >> 7;
    const int NIT = NCT * 16;          // 32-k chunks

    // prefetch chunk 0 into buffer 0
#pragma unroll
    for (int m = 0; m < 4; ++m) {
        CPASYNC16(sA + (aD0 + 1024u * m) * 4,          As0 + 16384u * m);
        CPASYNC16(sA + (4096u + aD0 + 1024u * m) * 4,  Bs0 + 16384u * m);
    }
    CPCOMMIT();

    int bufc = 0, bufp = 1;
    for (int it = 0; it < NIT; ++it) {
        if (it + 1 < NIT) {
            const int g1 = it + 1;
            const uint32_t boff = (uint32_t)bufp * BUF_WORDS;
            const uint32_t kb1  = (uint32_t)(g1 & 15) * 32u;
            const uint32_t cb1  = (uint32_t)(g1 >> 4) * 65536u;
#pragma unroll
            for (int m = 0; m < 4; ++m) {
                CPASYNC16(sA + (boff + aD0 + 1024u * m) * 4,
                          As0 + 16384u * m + kb1);
                CPASYNC16(sA + (boff + 4096u + aD0 + 1024u * m) * 4,
                          Bs0 + 16384u * m + cb1 + kb1);
            }
            CPCOMMIT();
            CPWAIT(1);
        } else {
            CPWAIT(0);
        }
        __syncthreads();   // single barrier per chunk (triple buffer)

        if ((it & 15) == 0) {
#pragma unroll
            for (int mt = 0; mt < 2; ++mt)
#pragma unroll
                for (int nt = 0; nt < 8; ++nt)
#pragma unroll
                    for (int c = 0; c < 4; ++c) acc[mt][nt][c] = 0.f;
        }

        {
            const uint32_t* A = SM + (uint32_t)bufc * BUF_WORDS;
            const uint32_t* B = A + 4096;
#pragma unroll
            for (int h = 0; h < 2; ++h) {
                const int j4s = ((h << 2) | tig) ^ keyg;
                uint32_t ah[2][4], am[2][4];
#pragma unroll
                for (int mt = 0; mt < 2; ++mt) {
                    const int r = wm * 32 + mt * 16 + gid;
                    uint4 v = *(const uint4*)(A + r * 32 + j4s * 4);
                    uint4 w = *(const uint4*)(A + (r + 8) * 32 + j4s * 4);
                    ah[mt][0] = v.x; am[mt][0] = v.y; ah[mt][2] = v.z; am[mt][2] = v.w;
                    ah[mt][1] = w.x; am[mt][1] = w.y; ah[mt][3] = w.z; am[mt][3] = w.w;
                }
#pragma unroll
                for (int nt = 0; nt < 8; ++nt) {
                    const int cr = wn * 64 + nt * 8 + gid;
                    uint4 b = *(const uint4*)(B + cr * 32 + j4s * 4);
#pragma unroll
                    for (int mt = 0; mt < 2; ++mt) {
                        MMA_BF16(acc[mt][nt], ah[mt], b.x, b.z);   // h*h
                        MMA_BF16(acc[mt][nt], ah[mt], b.y, b.w);   // h*m
                        MMA_BF16(acc[mt][nt], am[mt], b.x, b.z);   // m*h
                    }
                }
            }
        }

        if ((it & 15) == 15) {
            const int ct = it >> 4;
#pragma unroll
            for (int mt = 0; mt < 2; ++mt)
#pragma unroll
                for (int nt = 0; nt < 8; ++nt)
#pragma unroll
                    for (int c = 0; c < 4; ++c) {
                        const int col = ct * 128 + wn * 64 + nt * 8 + tig * 2 + (c & 1);
                        const int s   = mt * 2 + (c >> 1);
                        // x2-invariant ordering metric: e2 - 2*xe
                        float dd = __fmaf_rn(-2.0f, acc[mt][nt][c], __ldg(&en2[col]));
                        bool p = dd < b1d[s];
                        bool q = dd < b2d[s];
                        b2d[s] = p ? b1d[s] : (q ? dd  : b2d[s]);
                        b2i[s] = p ? b1i[s] : (q ? col : b2i[s]);
                        b1d[s] = p ? dd  : b1d[s];
                        b1i[s] = p ? col : b1i[s];
                    }
        }

        bufc = (bufc == 2) ? 0 : bufc + 1;
        bufp = (bufp == 2) ? 0 : bufp + 1;
    }

    // stream buffers dead; alias reduction arrays onto SM (barrier first)
    __syncthreads();
    float* sd1 = (float*)&SM[0];
    int*   si1 = (int*)  &SM[256];
    float* sd2 = (float*)&SM[512];
    int*   si2 = (int*)  &SM[768];

    // ---- reduction: across tig (shfl), then across warp_n (smem) ----
#pragma unroll
    for (int s = 0; s < 4; ++s) {
        float d1 = b1d[s], d2 = b2d[s];
        int   i1 = b1i[s], i2 = b2i[s];
#pragma unroll
        for (int off = 1; off < 4; off <<= 1) {
            float pd1 = __shfl_xor_sync(0xFFFFFFFFu, d1, off);
            int   pi1 = __shfl_xor_sync(0xFFFFFFFFu, i1, off);
            float pd2 = __shfl_xor_sync(0xFFFFFFFFu, d2, off);
            int   pi2 = __shfl_xor_sync(0xFFFFFFFFu, i2, off);
            merge2(d1, i1, d2, i2, pd1, pi1, pd2, pi2);
        }
        if (tig == 0) {
            const int row = wm * 32 + (s >> 1) * 16 + (s & 1) * 8 + gid;
            sd1[wn * 128 + row] = d1;  si1[wn * 128 + row] = i1;
            sd2[wn * 128 + row] = d2;  si2[wn * 128 + row] = i2;
        }
    }
    __syncthreads();

    if (tid < 128) {
        float d1 = sd1[tid], d2 = sd2[tid];
        int   i1 = si1[tid], i2 = si2[tid];
        merge2(d1, i1, d2, i2,
               sd1[128 + tid], si1[128 + tid], sd2[128 + tid], si2[128 + tid]);

        int winner = i1;
        if (d2 - d1 <= MARGIN) {
            // exact reference rescore of the near-tied pair
            const int row = rowBase + tid;
            int ia = min(i1, i2), ib = max(i1, i2);
            const float4* xr = (const float4*)(X + (size_t)row * D);
            const float4* ea = (const float4*)(Ecur + (size_t)ia * D);
            const float4* eb = (const float4*)(Ecur + (size_t)ib * D);
            float x2v = __ldg(&rn2[row]);
            float xea = 0.f, xeb = 0.f;
            if (idxPrev) {
                const float4* pr = (const float4*)(Eprev + (size_t)__ldg(&idxPrev[row]) * D);
                for (int k = 0; k < D / 4; ++k) {
                    float4 xv = __ldg(&xr[k]);
                    float4 pv = __ldg(&pr[k]);
                    float4 rv = make_float4(xv.x - pv.x, xv.y - pv.y,
                                            xv.z - pv.z, xv.w - pv.w);
                    float4 av = __ldg(&ea[k]);
                    float4 bv = __ldg(&eb[k]);
                    xea = __fmaf_rn(rv.x, av.x, xea); xea = __fmaf_rn(rv.y, av.y, xea);
                    xea = __fmaf_rn(rv.z, av.z, xea); xea = __fmaf_rn(rv.w, av.w, xea);
                    xeb = __fmaf_rn(rv.x, bv.x, xeb); xeb = __fmaf_rn(rv.y, bv.y, xeb);
                    xeb = __fmaf_rn(rv.z, bv.z, xeb); xeb = __fmaf_rn(rv.w, bv.w, xeb);
                }
            } else {
                for (int k = 0; k < D / 4; ++k) {
                    float4 rv = __ldg(&xr[k]);
                    float4 av = __ldg(&ea[k]);
                    float4 bv = __ldg(&eb[k]);
                    xea = __fmaf_rn(rv.x, av.x, xea); xea = __fmaf_rn(rv.y, av.y, xea);
                    xea = __fmaf_rn(rv.z, av.z, xea); xea = __fmaf_rn(rv.w, av.w, xea);
                    xeb = __fmaf_rn(rv.x, bv.x, xeb); xeb = __fmaf_rn(rv.y, bv.y, xeb);
                    xeb = __fmaf_rn(rv.z, bv.z, xeb); xeb = __fmaf_rn(rv.w, bv.w, xeb);
                }
            }
            float da = __fmaf_rn(-2.f, xea, __fadd_rn(x2v, __ldg(&en2[ia])));
            float db = __fmaf_rn(-2.f, xeb, __fadd_rn(x2v, __ldg(&en2[ib])));
            winner = (db < da) ? ib : ia;   // tie -> lower index ia
        }
        outIdx[rowBase + tid] = winner;
        if (outBuf) si1[tid] = winner;     // publish for the out tail
    }

    // ---- stage-2 tail: write final output for this CTA's 128 rows ----
    // out = fl(x + fl(fl(e0+e1) - x)) -- elementwise, order-free.
    if (outBuf) {
        __syncthreads();
        const int cidx = tid & 127;                  // float4 column 0..127
        for (int rr = (tid >> 7); rr < BM; rr += 2) {
            const int row = rowBase + rr;
            const int ca = __ldg(&idxPrev[row]);     // stage-1 code
            const int cb = si1[rr];                  // stage-2 code
            float4 xv = __ldg(&((const float4*)(X     + (size_t)row * D))[cidx]);
            float4 a  = __ldg(&((const float4*)(Eprev + (size_t)ca  * D))[cidx]);
            float4 b  = __ldg(&((const float4*)(Ecur  + (size_t)cb  * D))[cidx]);
            float4 o;
            o.x = __fadd_rn(xv.x, __fadd_rn(__fadd_rn(a.x, b.x), -xv.x));
            o.y = __fadd_rn(xv.y, __fadd_rn(__fadd_rn(a.y, b.y), -xv.y));
            o.z = __fadd_rn(xv.z, __fadd_rn(__fadd_rn(a.z, b.z), -xv.z));
            o.w = __fadd_rn(xv.w, __fadd_rn(__fadd_rn(a.w, b.w), -xv.w));
            ((float4*)(outBuf + (size_t)row * D))[cidx] = o;
        }
    }
}

// ---------------------------------------------------------------------------
// Fused: residual = X - E[idx] (exact fp32) -> packed bf16 words + ||R||^2.
// (kept as its own kernel: r2 summation order is part of the bit-exact recipe)
// ---------------------------------------------------------------------------
__global__ void residpack_kernel(const float* __restrict__ X, const float* __restrict__ E,
                                 const int* __restrict__ idx,
                                 uint32_t* __restrict__ Rpk, float* __restrict__ r2)
{
    int row = blockIdx.x;
    int t   = threadIdx.x;     // 0..127
    int c   = idx[row];
    float4 xv = ((const float4*)(X + (size_t)row * D))[t];
    float4 ev = ((const float4*)(E + (size_t)c   * D))[t];
    float4 rv = make_float4(xv.x - ev.x, xv.y - ev.y, xv.z - ev.z, xv.w - ev.w);

    {
        uint32_t* dst = Rpk + (size_t)row * WPR;
        int blk = t >> 2;
        int a   = t & 3;
        uint32_t whi0 = bf16pack(rv.x, rv.y);
        uint32_t wmi0 = bf16pack(rv.x - bf16round(rv.x), rv.y - bf16round(rv.y));
        uint32_t whi1 = bf16pack(rv.z, rv.w);
        uint32_t wmi1 = bf16pack(rv.z - bf16round(rv.z), rv.w - bf16round(rv.w));
        int w0 = (a < 2) ? 8 * a     : 8 * (a - 2) + 2;
        int w1 = (a < 2) ? 8 * a + 4 : 8 * (a - 2) + 6;
        dst[blk * 16 + w0]     = whi0;
        dst[blk * 16 + w0 + 1] = wmi0;
        dst[blk * 16 + w1]     = whi1;
        dst[blk * 16 + w1 + 1] = wmi1;
    }

    float s = rv.x * rv.x + rv.y * rv.y + rv.z * rv.z + rv.w * rv.w;
#pragma unroll
    for (int o = 16; o; o >>= 1) s += __shfl_down_sync(0xFFFFFFFFu, s, o);
    __shared__ float red[4];
    if ((t & 31) == 0) red[t >> 5] = s;
    __syncthreads();
    if (t == 0) r2[row] = red[0] + red[1] + red[2] + red[3];
}

// ---------------------------------------------------------------------------
extern "C" void kernel_launch(void* const* d_in, const int* in_sizes, int n_in,
                              void* d_out, int out_size)
{
    const float* x  = (const float*)d_in[0];
    const float* e0 = (const float*)d_in[1];
    const float* e1 = (const float*)d_in[2];
    float* out = (float*)d_out;

    int rows = in_sizes[0] / D;   // 32768
    int nc   = in_sizes[1] / D;   // 1024

    uint32_t *papk, *pe0pk, *pe1pk;
    float *px2, *pr2, *pe2a, *pe2b;
    int   *pi0, *pi1;
    cudaGetSymbolAddress((void**)&papk,  g_apk);
    cudaGetSymbolAddress((void**)&pe0pk, g_e0pk);
    cudaGetSymbolAddress((void**)&pe1pk, g_e1pk);
    cudaGetSymbolAddress((void**)&px2,   g_x2);
    cudaGetSymbolAddress((void**)&pr2,   g_r2);
    cudaGetSymbolAddress((void**)&pe2a,  g_e2a);
    cudaGetSymbolAddress((void**)&pe2b,  g_e2b);
    cudaGetSymbolAddress((void**)&pi0,   g_idx0);
    cudaGetSymbolAddress((void**)&pi1,   g_idx1);

    cudaFuncSetAttribute(stage_mma_kernel,
                         cudaFuncAttributeMaxDynamicSharedMemorySize, SMEM_DYN);

    packnorm3_kernel<<<(rows + 2 * nc + 7) / 8, 256>>>(x, papk, px2,
                                                       e0, pe0pk, pe2a,
                                                       e1, pe1pk, pe2b,
                                                       rows, nc);
    stage_mma_kernel<<<rows / BM, 256, SMEM_DYN>>>(papk, pe0pk,
                                                   x, nullptr, nullptr, e0,
                                                   px2, pe2a, pi0, nc, nullptr);
    residpack_kernel<<<rows, 128>>>(x, e0, pi0, papk, pr2);
    stage_mma_kernel<<<rows / BM, 256, SMEM_DYN>>>(papk, pe1pk,
                                                   x, e0, pi0, e1,
                                                   pr2, pe2b, pi1, nc, out);
}